// round 2
// baseline (speedup 1.0000x reference)
#include <cuda_runtime.h>

#define NCLS 80
#define NCH  81
#define TK   100
#define BN   8
#define CN   256
#define HN   128
#define WN   128
#define HW   (HN*WN)

// ---------------- scratch (device globals: sanctioned, no allocs) ----------
__device__ float g_y[(size_t)BN*CN*HN*WN];      // relu(conv3x3) output
__device__ float g_w1t[CN*9*CN];                // w1 transposed: [cin][tap][oc]
__device__ float g_w2t[CN*NCH];                 // w2 transposed: [cin][oc]
__device__ float g_pstar[BN*HW];
__device__ int   g_cls[BN*HW];
__device__ float g_scores[BN*HW];
__device__ int   g_topidx[BN*TK];

// ---------------- f32x2 helpers (Blackwell packed fp32) --------------------
__device__ __forceinline__ unsigned long long pk2(float lo, float hi){
    unsigned long long r;
    asm("mov.b64 %0, {%1,%2};" : "=l"(r) : "f"(lo), "f"(hi));
    return r;
}
__device__ __forceinline__ void upk2(unsigned long long v, float& lo, float& hi){
    asm("mov.b64 {%0,%1}, %2;" : "=f"(lo), "=f"(hi) : "l"(v));
}
__device__ __forceinline__ unsigned long long f2fma(unsigned long long a,
                                                    unsigned long long b,
                                                    unsigned long long c){
    unsigned long long d;
    asm("fma.rn.f32x2 %0, %1, %2, %3;" : "=l"(d) : "l"(a), "l"(b), "l"(c));
    return d;
}

// ---------------- K0: weight transposes ------------------------------------
__global__ void k0_transpose(const float* __restrict__ w1,
                             const float* __restrict__ w2){
    int t = blockIdx.x*256 + threadIdx.x;
    if (t < CN*9*CN){
        int cin = t/(9*CN); int tap = (t/CN)%9; int oc = t%CN;
        g_w1t[t] = w1[(oc*CN + cin)*9 + tap];
    }
    if (t < CN*NCH){
        int cin = t/NCH; int oc = t%NCH;
        g_w2t[t] = w2[oc*CN + cin];
    }
}

// ---------------- K1: conv3x3 + bias + relu (f32x2, pipelined) -------------
// block: 64 oc x (8h x 16w) tile; 256 threads: tid = [ocg(4b)][row(3b)][pxg(1b)]
// each thread: 4 oc x 8 horizontally-adjacent pixels (4 f32x2 lanes)
// double-buffered smem, register prefetch, zero-MOV packed operands:
//  - weights pre-duplicated {w,w} in smem  -> LDS.64, no packing
//  - inputs stored normal + shifted-by-1   -> both P0/P1 are aligned LDS.64
#define SR 22   // smem row stride (floats); 22d mod 32 avoids {0,8} for d=1..7
__global__ __launch_bounds__(256,2) void k1_conv3(const float* __restrict__ x,
                                                  const float* __restrict__ b1){
    __shared__ __align__(16) float sIn [2][10][SR];
    __shared__ __align__(16) float sInS[2][10][SR];            // shifted by +1 col
    __shared__ __align__(16) unsigned long long sW2[2][9][64]; // {w,w} pairs

    const int tid = threadIdx.x;
    const int bx  = blockIdx.x;
    const int h0  = (bx>>3)*8, w0 = (bx&7)*16;
    const int oc_base = blockIdx.y*64;
    const int b   = blockIdx.z;
    const int pxg = tid & 1, row = (tid>>1)&7, ocg = tid>>4;
    const int c0  = pxg*8;
    const float* xb = x + (size_t)b*CN*HW;

    unsigned long long acc[4][4];
    #pragma unroll
    for (int o=0;o<4;o++)
        #pragma unroll
        for (int q=0;q<4;q++) acc[o][q] = 0ull;

    // input-fill coords (tid<180)
    const int lr = tid/18, lc = tid%18;
    const int gh = h0 - 1 + lr, gw = w0 - 1 + lc;
    const bool inb = (tid<180) && (gh>=0) && (gh<HN) && (gw>=0) && (gw<WN);
    const float* xptr = xb + (size_t)gh*WN + gw;   // + cin*HW per iter

    // weight-fill coords (tid<144): tap = tid/16, quad = tid%16
    const int wtap = tid>>4, wq = tid&15;
    const float* wptr = g_w1t + (size_t)wtap*CN + oc_base + wq*4; // + cin*9*CN per iter

    // ---- prefetch cin = 0 ----
    float  inv = inb ? xptr[0] : 0.f;
    float4 wv  = (tid<144) ? *(const float4*)wptr : make_float4(0,0,0,0);

    for (int cin=0; cin<CN; cin++){
        const int buf = cin & 1;
        // stage prefetched data into smem
        if (tid < 180){
            sIn[buf][lr][lc] = inv;
            if (lc > 0) sInS[buf][lr][lc-1] = inv;
        }
        if (tid < 144){
            sW2[buf][wtap][wq*4+0] = pk2(wv.x, wv.x);
            sW2[buf][wtap][wq*4+1] = pk2(wv.y, wv.y);
            sW2[buf][wtap][wq*4+2] = pk2(wv.z, wv.z);
            sW2[buf][wtap][wq*4+3] = pk2(wv.w, wv.w);
        }
        __syncthreads();

        // issue prefetch for next cin (latency hidden under compute)
        if (cin + 1 < CN){
            inv = inb ? xptr[(size_t)(cin+1)*HW] : 0.f;
            if (tid < 144) wv = *(const float4*)(wptr + (size_t)(cin+1)*9*CN);
        }

        // compute
        #pragma unroll
        for (int ky=0; ky<3; ky++){
            const float* rp = &sIn [buf][row+ky][c0];
            const float* rq = &sInS[buf][row+ky][c0];
            unsigned long long P0[5], P1[4];
            #pragma unroll
            for (int q=0;q<5;q++) P0[q] = *(const unsigned long long*)(rp + 2*q);
            #pragma unroll
            for (int q=0;q<4;q++) P1[q] = *(const unsigned long long*)(rq + 2*q);
            #pragma unroll
            for (int o=0;o<4;o++){
                const int ocl = ocg*4 + o;
                const unsigned long long wpa = sW2[buf][ky*3+0][ocl];
                const unsigned long long wpb = sW2[buf][ky*3+1][ocl];
                const unsigned long long wpc = sW2[buf][ky*3+2][ocl];
                #pragma unroll
                for (int q=0;q<4;q++){
                    acc[o][q] = f2fma(wpa, P0[q],   acc[o][q]);
                    acc[o][q] = f2fma(wpb, P1[q],   acc[o][q]);
                    acc[o][q] = f2fma(wpc, P0[q+1], acc[o][q]);
                }
            }
        }
    }

    const int oh = h0 + row;
    #pragma unroll
    for (int o=0;o<4;o++){
        const int oc = oc_base + ocg*4 + o;
        const float bias = b1[oc];
        float* yp = g_y + (size_t)(b*CN + oc)*HW + oh*WN + w0 + c0;
        #pragma unroll
        for (int q=0;q<4;q++){
            float lo, hi; upk2(acc[o][q], lo, hi);
            lo = fmaxf(lo + bias, 0.f);
            hi = fmaxf(hi + bias, 0.f);
            *(float2*)(yp + 2*q) = make_float2(lo, hi);
        }
    }
}

// ---------------- K2: conv1x1 + bias + softmax stats + logits out ----------
__global__ __launch_bounds__(256) void k2_conv1(const float* __restrict__ b2,
                                                float* __restrict__ out){
    __shared__ __align__(16) float ws2[32][84];
    const int tid = threadIdx.x;
    const int gp  = blockIdx.x*256 + tid;
    const int b   = gp >> 14, hw = gp & (HW-1);

    float acc[NCH];
    #pragma unroll
    for (int o=0;o<NCH;o++) acc[o] = 0.f;

    const float* yb = g_y + (size_t)b*CN*HW + hw;
    for (int cc=0; cc<CN; cc+=32){
        __syncthreads();
        #pragma unroll
        for (int i=tid; i<32*NCH; i+=256)
            ws2[i/NCH][i%NCH] = g_w2t[(cc + i/NCH)*NCH + (i%NCH)];
        __syncthreads();
        #pragma unroll 4
        for (int cl=0; cl<32; cl++){
            const float yv = yb[(size_t)(cc+cl)*HW];
            #pragma unroll
            for (int o4=0;o4<20;o4++){
                float4 w4 = *(const float4*)&ws2[cl][o4*4];
                acc[o4*4+0] += yv*w4.x; acc[o4*4+1] += yv*w4.y;
                acc[o4*4+2] += yv*w4.z; acc[o4*4+3] += yv*w4.w;
            }
            acc[80] += yv*ws2[cl][80];
        }
    }
    #pragma unroll
    for (int o=0;o<NCH;o++) acc[o] += b2[o];

    float m = acc[0];
    #pragma unroll
    for (int o=1;o<NCH;o++) m = fmaxf(m, acc[o]);
    float s = 0.f;
    #pragma unroll
    for (int o=0;o<NCH;o++) s += expf(acc[o]-m);
    int cls = 0; float best = acc[0];
    #pragma unroll
    for (int o=1;o<NCLS;o++) if (acc[o] > best){ best = acc[o]; cls = o; }

    g_pstar[gp] = expf(best - m)/s;
    g_cls[gp]   = cls;

    float* lo = out + 409600 + (size_t)b*NCH*HW + hw;
    #pragma unroll
    for (int o=0;o<NCH;o++) lo[(size_t)o*HW] = acc[o];
}

// ---------------- K3: local-max boost + score map --------------------------
__global__ void k3_boost(){
    const int gp = blockIdx.x*256 + threadIdx.x;
    const int b = gp>>14, hw = gp&(HW-1);
    const int h = hw>>7,  w  = hw&127;
    const float p = g_pstar[gp];
    const int   c = g_cls[gp];
    bool ok = (p >= 1e-6f);
    #pragma unroll
    for (int dy=-1; dy<=1; dy++)
        #pragma unroll
        for (int dx=-1; dx<=1; dx++){
            if (dy==0 && dx==0) continue;
            int nh = h+dy, nw = w+dx;
            if (nh<0 || nh>=HN || nw<0 || nw>=WN) continue;
            int n = (b<<14) + nh*WN + nw;
            if (g_cls[n]==c && p < g_pstar[n]) ok = false;
        }
    g_scores[gp] = p + (ok ? 1.f : 0.f);
}

// ---------------- K4: per-batch top-100 via bitonic sort -------------------
__global__ void k4_topk(){
    extern __shared__ unsigned long long sk[];
    const int N = HW;
    const int b = blockIdx.x, tid = threadIdx.x;
    for (int i=tid; i<N; i+=1024){
        unsigned sb = __float_as_uint(g_scores[(b<<14)+i]);  // scores > 0
        sk[i] = ((unsigned long long)sb<<32) | (unsigned)(0xFFFFFFFFu - (unsigned)i);
    }
    __syncthreads();
    for (int k=2; k<=N; k<<=1){
        for (int j=k>>1; j>0; j>>=1){
            for (int i=tid; i<N; i+=1024){
                int ixj = i^j;
                if (ixj > i){
                    unsigned long long a = sk[i], c = sk[ixj];
                    bool up = (i&k)==0;
                    if (up ? (a<c) : (a>c)){ sk[i]=c; sk[ixj]=a; }
                }
            }
            __syncthreads();
        }
    }
    if (tid < TK){
        unsigned low = (unsigned)sk[tid];
        g_topidx[b*TK + tid] = (int)(0xFFFFFFFFu - low);
    }
}

// ---------------- K5: gather proposals + pos embeddings --------------------
__global__ void k5_gather(const float* __restrict__ x,
                          const float* __restrict__ pe,
                          float* __restrict__ out){
    const int t = blockIdx.x*256 + threadIdx.x;
    if (t >= BN*CN*TK) return;
    const int k = t % TK;
    const int c = (t / TK) % CN;
    const int b = t / (TK*CN);
    const int idx = g_topidx[b*TK + k];
    out[t]            = x [(size_t)(b*CN + c)*HW + idx];
    out[BN*CN*TK + t] = pe[(size_t)c*HW + idx];
}

// ---------------- launch ----------------------------------------------------
extern "C" void kernel_launch(void* const* d_in, const int* in_sizes, int n_in,
                              void* d_out, int out_size){
    const float* x  = (const float*)d_in[0];
    const float* pe = (const float*)d_in[1];
    const float* w1 = (const float*)d_in[2];
    const float* b1 = (const float*)d_in[3];
    const float* w2 = (const float*)d_in[4];
    const float* b2 = (const float*)d_in[5];
    float* out = (float*)d_out;

    cudaFuncSetAttribute(k4_topk, cudaFuncAttributeMaxDynamicSharedMemorySize, 131072);

    k0_transpose<<<(CN*9*CN + 255)/256, 256>>>(w1, w2);

    dim3 g1(128, 4, 8);                 // 16x8 spatial tiles, 4 oc-tiles, 8 batches
    k1_conv3<<<g1, 256>>>(x, b1);

    k2_conv1<<<(BN*HW)/256, 256>>>(b2, out);
    k3_boost<<<(BN*HW)/256, 256>>>();
    k4_topk<<<BN, 1024, 131072>>>();
    k5_gather<<<(BN*CN*TK + 255)/256, 256>>>(x, pe, out);
}

// round 3
// speedup vs baseline: 1.1649x; 1.1649x over previous
#include <cuda_runtime.h>

#define NCLS 80
#define NCH  81
#define TK   100
#define BN   8
#define CN   256
#define HN   128
#define WN   128
#define HW   (HN*WN)

// ---------------- scratch (device globals: sanctioned, no allocs) ----------
__device__ float g_y[(size_t)BN*CN*HN*WN];      // relu(conv3x3) output
__device__ float g_w1t[CN*9*CN];                // w1 transposed: [cin][tap][oc]
__device__ float g_w2t[CN*NCH];                 // w2 transposed: [cin][oc]
__device__ float g_pstar[BN*HW];
__device__ int   g_cls[BN*HW];
__device__ float g_scores[BN*HW];
__device__ int   g_topidx[BN*TK];

// ---------------- f32x2 helpers (Blackwell packed fp32) --------------------
__device__ __forceinline__ unsigned long long pk2(float lo, float hi){
    unsigned long long r;
    asm("mov.b64 %0, {%1,%2};" : "=l"(r) : "f"(lo), "f"(hi));
    return r;
}
__device__ __forceinline__ void upk2(unsigned long long v, float& lo, float& hi){
    asm("mov.b64 {%0,%1}, %2;" : "=f"(lo), "=f"(hi) : "l"(v));
}
__device__ __forceinline__ unsigned long long f2fma(unsigned long long a,
                                                    unsigned long long b,
                                                    unsigned long long c){
    unsigned long long d;
    asm("fma.rn.f32x2 %0, %1, %2, %3;" : "=l"(d) : "l"(a), "l"(b), "l"(c));
    return d;
}

// ---------------- K0: weight transposes ------------------------------------
__global__ void k0_transpose(const float* __restrict__ w1,
                             const float* __restrict__ w2){
    int t = blockIdx.x*256 + threadIdx.x;
    if (t < CN*9*CN){
        int cin = t/(9*CN); int tap = (t/CN)%9; int oc = t%CN;
        g_w1t[t] = w1[(oc*CN + cin)*9 + tap];
    }
    if (t < CN*NCH){
        int cin = t/NCH; int oc = t%NCH;
        g_w2t[t] = w2[oc*CN + cin];
    }
}

// ---------------- K1: conv3x3 + bias + relu (f32x2, 8oc x 8px) -------------
// block: 128 oc x (8h x 16w) tile; 256 threads: tid = [ocg(4b)][row(3b)][pxg(1b)]
// each thread: 8 oc x 8 horizontally-adjacent pixels (32 f32x2 accumulators)
// double-buffered smem + register prefetch hides gmem latency;
// weights pre-duplicated {w,w} u64 in smem (broadcast LDS.64, no per-FMA movs);
// inputs: float4 LDS, even pairs pack free via register pairing.
__global__ __launch_bounds__(256,2) void k1_conv3(const float* __restrict__ x,
                                                  const float* __restrict__ b1){
    __shared__ __align__(16) float sIn[2][10][20];
    __shared__ __align__(16) unsigned long long sW2[2][9][128]; // {w,w} pairs

    const int tid = threadIdx.x;
    const int bx  = blockIdx.x;
    const int h0  = (bx>>3)*8, w0 = (bx&7)*16;
    const int oc_base = blockIdx.y*128;
    const int b   = blockIdx.z;
    const int pxg = tid & 1, row = (tid>>1)&7, ocg = tid>>4;
    const int c0  = pxg*8;
    const float* xb = x + (size_t)b*CN*HW;

    unsigned long long acc[8][4];
    #pragma unroll
    for (int o=0;o<8;o++)
        #pragma unroll
        for (int q=0;q<4;q++) acc[o][q] = 0ull;

    // input-fill coords (tid<180)
    const int lr = tid/18, lc = tid%18;
    const int gh = h0 - 1 + lr, gw = w0 - 1 + lc;
    const bool inb = (tid<180) && (gh>=0) && (gh<HN) && (gw>=0) && (gw<WN);
    const float* xptr = xb + (size_t)gh*WN + gw;   // + cin*HW per iter

    // weight-fill coords (tid<144): tap = tid/16, grp = tid%16 -> 8 oc each
    const int wtap = tid>>4, wg = tid&15;
    const float* wptr = g_w1t + (size_t)wtap*CN + oc_base + wg*8; // + cin*9*CN per iter

    // ---- prefetch cin = 0 ----
    float  inv = inb ? xptr[0] : 0.f;
    float4 wv0 = make_float4(0,0,0,0), wv1 = make_float4(0,0,0,0);
    if (tid < 144){ wv0 = *(const float4*)wptr; wv1 = *(const float4*)(wptr+4); }

    for (int cin=0; cin<CN; cin++){
        const int buf = cin & 1;
        if (tid < 180) sIn[buf][lr][lc] = inv;
        if (tid < 144){
            unsigned long long* wd = &sW2[buf][wtap][wg*8];
            wd[0]=pk2(wv0.x,wv0.x); wd[1]=pk2(wv0.y,wv0.y);
            wd[2]=pk2(wv0.z,wv0.z); wd[3]=pk2(wv0.w,wv0.w);
            wd[4]=pk2(wv1.x,wv1.x); wd[5]=pk2(wv1.y,wv1.y);
            wd[6]=pk2(wv1.z,wv1.z); wd[7]=pk2(wv1.w,wv1.w);
        }
        __syncthreads();

        // issue next cin's prefetch (latency hidden under compute below)
        if (cin + 1 < CN){
            inv = inb ? xptr[(size_t)(cin+1)*HW] : 0.f;
            if (tid < 144){
                const float* wp = wptr + (size_t)(cin+1)*9*CN;
                wv0 = *(const float4*)wp; wv1 = *(const float4*)(wp+4);
            }
        }

        #pragma unroll
        for (int ky=0; ky<3; ky++){
            const float* rp = &sIn[buf][row+ky][c0];
            float4 A  = *(const float4*)rp;
            float4 Bv = *(const float4*)(rp+4);
            float2 Cv = *(const float2*)(rp+8);
            unsigned long long P0[5], P1[4];
            P0[0]=pk2(A.x,A.y);  P0[1]=pk2(A.z,A.w);
            P0[2]=pk2(Bv.x,Bv.y);P0[3]=pk2(Bv.z,Bv.w); P0[4]=pk2(Cv.x,Cv.y);
            P1[0]=pk2(A.y,A.z);  P1[1]=pk2(A.w,Bv.x);
            P1[2]=pk2(Bv.y,Bv.z);P1[3]=pk2(Bv.w,Cv.x);
            #pragma unroll
            for (int o=0;o<8;o++){
                const int ocl = ocg*8 + o;
                const unsigned long long wpa = sW2[buf][ky*3+0][ocl];
                const unsigned long long wpb = sW2[buf][ky*3+1][ocl];
                const unsigned long long wpc = sW2[buf][ky*3+2][ocl];
                #pragma unroll
                for (int q=0;q<4;q++){
                    acc[o][q] = f2fma(wpa, P0[q],   acc[o][q]);
                    acc[o][q] = f2fma(wpb, P1[q],   acc[o][q]);
                    acc[o][q] = f2fma(wpc, P0[q+1], acc[o][q]);
                }
            }
        }
    }

    const int oh = h0 + row;
    #pragma unroll
    for (int o=0;o<8;o++){
        const int oc = oc_base + ocg*8 + o;
        const float bias = b1[oc];
        float* yp = g_y + (size_t)(b*CN + oc)*HW + oh*WN + w0 + c0;
        #pragma unroll
        for (int q=0;q<4;q++){
            float lo, hi; upk2(acc[o][q], lo, hi);
            lo = fmaxf(lo + bias, 0.f);
            hi = fmaxf(hi + bias, 0.f);
            *(float2*)(yp + 2*q) = make_float2(lo, hi);
        }
    }
}

// ---------------- K2: conv1x1 + bias + softmax stats + logits out ----------
__global__ __launch_bounds__(256) void k2_conv1(const float* __restrict__ b2,
                                                float* __restrict__ out){
    __shared__ __align__(16) float ws2[32][84];
    const int tid = threadIdx.x;
    const int gp  = blockIdx.x*256 + tid;
    const int b   = gp >> 14, hw = gp & (HW-1);

    float acc[NCH];
    #pragma unroll
    for (int o=0;o<NCH;o++) acc[o] = 0.f;

    const float* yb = g_y + (size_t)b*CN*HW + hw;
    for (int cc=0; cc<CN; cc+=32){
        __syncthreads();
        #pragma unroll
        for (int i=tid; i<32*NCH; i+=256)
            ws2[i/NCH][i%NCH] = g_w2t[(cc + i/NCH)*NCH + (i%NCH)];
        __syncthreads();
        #pragma unroll 4
        for (int cl=0; cl<32; cl++){
            const float yv = yb[(size_t)(cc+cl)*HW];
            #pragma unroll
            for (int o4=0;o4<20;o4++){
                float4 w4 = *(const float4*)&ws2[cl][o4*4];
                acc[o4*4+0] += yv*w4.x; acc[o4*4+1] += yv*w4.y;
                acc[o4*4+2] += yv*w4.z; acc[o4*4+3] += yv*w4.w;
            }
            acc[80] += yv*ws2[cl][80];
        }
    }
    #pragma unroll
    for (int o=0;o<NCH;o++) acc[o] += b2[o];

    float m = acc[0];
    #pragma unroll
    for (int o=1;o<NCH;o++) m = fmaxf(m, acc[o]);
    float s = 0.f;
    #pragma unroll
    for (int o=0;o<NCH;o++) s += expf(acc[o]-m);
    int cls = 0; float best = acc[0];
    #pragma unroll
    for (int o=1;o<NCLS;o++) if (acc[o] > best){ best = acc[o]; cls = o; }

    g_pstar[gp] = expf(best - m)/s;
    g_cls[gp]   = cls;

    float* lo = out + 409600 + (size_t)b*NCH*HW + hw;
    #pragma unroll
    for (int o=0;o<NCH;o++) lo[(size_t)o*HW] = acc[o];
}

// ---------------- K3: local-max boost + score map --------------------------
__global__ void k3_boost(){
    const int gp = blockIdx.x*256 + threadIdx.x;
    const int b = gp>>14, hw = gp&(HW-1);
    const int h = hw>>7,  w  = hw&127;
    const float p = g_pstar[gp];
    const int   c = g_cls[gp];
    bool ok = (p >= 1e-6f);
    #pragma unroll
    for (int dy=-1; dy<=1; dy++)
        #pragma unroll
        for (int dx=-1; dx<=1; dx++){
            if (dy==0 && dx==0) continue;
            int nh = h+dy, nw = w+dx;
            if (nh<0 || nh>=HN || nw<0 || nw>=WN) continue;
            int n = (b<<14) + nh*WN + nw;
            if (g_cls[n]==c && p < g_pstar[n]) ok = false;
        }
    g_scores[gp] = p + (ok ? 1.f : 0.f);
}

// ---------------- K4: per-batch top-100 via bitonic sort -------------------
__global__ void k4_topk(){
    extern __shared__ unsigned long long sk[];
    const int N = HW;
    const int b = blockIdx.x, tid = threadIdx.x;
    for (int i=tid; i<N; i+=1024){
        unsigned sb = __float_as_uint(g_scores[(b<<14)+i]);  // scores > 0
        sk[i] = ((unsigned long long)sb<<32) | (unsigned)(0xFFFFFFFFu - (unsigned)i);
    }
    __syncthreads();
    for (int k=2; k<=N; k<<=1){
        for (int j=k>>1; j>0; j>>=1){
            for (int i=tid; i<N; i+=1024){
                int ixj = i^j;
                if (ixj > i){
                    unsigned long long a = sk[i], c = sk[ixj];
                    bool up = (i&k)==0;
                    if (up ? (a<c) : (a>c)){ sk[i]=c; sk[ixj]=a; }
                }
            }
            __syncthreads();
        }
    }
    if (tid < TK){
        unsigned low = (unsigned)sk[tid];
        g_topidx[b*TK + tid] = (int)(0xFFFFFFFFu - low);
    }
}

// ---------------- K5: gather proposals + pos embeddings --------------------
__global__ void k5_gather(const float* __restrict__ x,
                          const float* __restrict__ pe,
                          float* __restrict__ out){
    const int t = blockIdx.x*256 + threadIdx.x;
    if (t >= BN*CN*TK) return;
    const int k = t % TK;
    const int c = (t / TK) % CN;
    const int b = t / (TK*CN);
    const int idx = g_topidx[b*TK + k];
    out[t]            = x [(size_t)(b*CN + c)*HW + idx];
    out[BN*CN*TK + t] = pe[(size_t)c*HW + idx];
}

// ---------------- launch ----------------------------------------------------
extern "C" void kernel_launch(void* const* d_in, const int* in_sizes, int n_in,
                              void* d_out, int out_size){
    const float* x  = (const float*)d_in[0];
    const float* pe = (const float*)d_in[1];
    const float* w1 = (const float*)d_in[2];
    const float* b1 = (const float*)d_in[3];
    const float* w2 = (const float*)d_in[4];
    const float* b2 = (const float*)d_in[5];
    float* out = (float*)d_out;

    cudaFuncSetAttribute(k4_topk, cudaFuncAttributeMaxDynamicSharedMemorySize, 131072);

    k0_transpose<<<(CN*9*CN + 255)/256, 256>>>(w1, w2);

    dim3 g1(128, 2, 8);                 // 16x8 spatial tiles, 2 oc-blocks of 128, 8 batches
    k1_conv3<<<g1, 256>>>(x, b1);

    k2_conv1<<<(BN*HW)/256, 256>>>(b2, out);
    k3_boost<<<(BN*HW)/256, 256>>>();
    k4_topk<<<BN, 1024, 131072>>>();
    k5_gather<<<(BN*CN*TK + 255)/256, 256>>>(x, pe, out);
}

// round 6
// speedup vs baseline: 2.6862x; 2.3060x over previous
#include <cuda_runtime.h>
#include <cuda_fp16.h>
#include <cstdint>

#define NCLS 80
#define NCH  81
#define TK   100
#define BN   8
#define CN   256
#define HN   128
#define WN   128
#define HW   (HN*WN)
#define PP   130
#define NPX  (PP*PP)

// ---------------- scratch (device globals) ---------------------------------
__device__ __half g_xh[(size_t)BN*NPX*CN];   // NHWC padded, fp16-hi
__device__ __half g_xl[(size_t)BN*NPX*CN];   // NHWC padded, fp16-lo
__device__ __half g_wh[9*CN*CN];             // [tap][oc][cin] fp16-hi
__device__ __half g_wl[9*CN*CN];             // [tap][oc][cin] fp16-lo
__device__ float  g_y[(size_t)BN*HW*CN];     // relu(conv3x3), NHWC
__device__ float  g_w2t[CN*NCH];
__device__ float  g_pstar[BN*HW];
__device__ int    g_cls[BN*HW];
__device__ float  g_scores[BN*HW];
__device__ int    g_topidx[BN*TK];

// ---------------- PTX helpers ----------------------------------------------
__device__ __forceinline__ uint32_t smem_u32(const void* p){
    uint32_t a;
    asm("{ .reg .u64 t; cvta.to.shared.u64 t, %1; cvt.u32.u64 %0, t; }" : "=r"(a) : "l"(p));
    return a;
}
__device__ __forceinline__ void cpa16(uint32_t dst, const void* src){
    asm volatile("cp.async.cg.shared.global [%0], [%1], 16;" :: "r"(dst), "l"(src));
}
#define CP_COMMIT() asm volatile("cp.async.commit_group;" ::: "memory")
#define CP_WAIT1()  asm volatile("cp.async.wait_group 1;" ::: "memory")
#define CP_WAIT0()  asm volatile("cp.async.wait_group 0;" ::: "memory")

__device__ __forceinline__ void mma16816(float* d, const uint32_t* a, const uint32_t* b){
    asm volatile("mma.sync.aligned.m16n8k16.row.col.f32.f16.f16.f32 "
        "{%0,%1,%2,%3}, {%4,%5,%6,%7}, {%8,%9}, {%0,%1,%2,%3};"
        : "+f"(d[0]), "+f"(d[1]), "+f"(d[2]), "+f"(d[3])
        : "r"(a[0]), "r"(a[1]), "r"(a[2]), "r"(a[3]), "r"(b[0]), "r"(b[1]));
}

// ---------------- T0: NCHW -> padded NHWC fp16 hi/lo ------------------------
__global__ __launch_bounds__(256) void t_half(const float* __restrict__ x){
    __shared__ float s[256][33];
    const int b = blockIdx.y;
    const int px0 = blockIdx.x*32;
    const int tid = threadIdx.x;
    const int pxl = tid & 31, cg = tid >> 5;
    const int p = px0 + pxl;
    const int ph = p / PP, pw = p % PP;
    const bool in = (p < NPX) && ph >= 1 && ph <= 128 && pw >= 1 && pw <= 128;
    const float* xp = x + (size_t)b*CN*HW + (size_t)(ph-1)*WN + (pw-1);
    #pragma unroll 8
    for (int i=0;i<32;i++){
        int c = i*8 + cg;
        s[c][pxl] = in ? xp[(size_t)c*HW] : 0.f;
    }
    __syncthreads();
    for (int j=0;j<32;j++){
        int px = px0 + j;
        if (px >= NPX) break;
        float v  = s[tid][j];
        __half hi = __float2half_rn(v);
        __half lo = __float2half_rn(v - __half2float(hi));
        size_t o = ((size_t)b*NPX + px)*CN + tid;
        g_xh[o] = hi;
        g_xl[o] = lo;
    }
}

// ---------------- K0: weight prep + w2t -------------------------------------
__global__ void k0_wprep(const float* __restrict__ w1,
                         const float* __restrict__ w2){
    int t = blockIdx.x*256 + threadIdx.x;
    if (t < 9*CN*CN){
        int tap = t / (CN*CN);
        int r   = t % (CN*CN);
        int oc  = r / CN;
        int cin = r % CN;
        float v  = w1[((size_t)oc*CN + cin)*9 + tap];
        __half hi = __float2half_rn(v);
        __half lo = __float2half_rn(v - __half2float(hi));
        g_wh[t] = hi;     // layout [tap][oc][cin]
        g_wl[t] = lo;
    }
    if (t < CN*NCH){
        int cin = t/NCH, oc = t%NCH;
        g_w2t[t] = w2[oc*CN + cin];
    }
}

// ---------------- K1: conv3x3 via mma.sync fp16 split -----------------------
// grid (128 h, 2 ntile, 8 b); 256 threads = 8 warps (2M x 4N), warp tile m64n32.
// K-loop: 144 steps (9 taps x 16 cin-chunks of 16). 3-stage cp.async pipeline.
// smem stage: Ah[128][24] Al Bh Bl (fp16, 48B rows) = 24KB; x3 = 72KB dynamic.
#define STG_SZ 24576u
#define AH_OFF 0u
#define AL_OFF 6144u
#define BH_OFF 12288u
#define BL_OFF 18432u

__global__ __launch_bounds__(256,2) void kmma(const float* __restrict__ b1){
    extern __shared__ __align__(16) char smem[];
    const uint32_t sb = smem_u32(smem);
    const int tid  = threadIdx.x;
    const int lane = tid & 31, wid = tid >> 5;
    const int wm = wid >> 2, wn = wid & 3;
    const int h  = blockIdx.x;
    const int ocb = blockIdx.y * 128;
    const int bb = blockIdx.z;

    const int lrow = tid >> 1, lpart = tid & 1;    // cp.async: 2 threads/row
    const uint32_t dstoff = lrow*48u + lpart*16u;

    auto load_stage = [&](int g, int buf){
        const int tap = g >> 4, kc = g & 15;
        const int ky = tap/3, kx = tap%3;
        const uint32_t sbase = sb + buf*STG_SZ;
        const size_t apix = (size_t)bb*NPX + (size_t)(h + ky)*PP + kx + lrow;
        const size_t aoff = apix*CN + kc*16 + lpart*8;
        cpa16(sbase + AH_OFF + dstoff, g_xh + aoff);
        cpa16(sbase + AL_OFF + dstoff, g_xl + aoff);
        const size_t boff = ((size_t)tap*CN + ocb + lrow)*CN + kc*16 + lpart*8;
        cpa16(sbase + BH_OFF + dstoff, g_wh + boff);
        cpa16(sbase + BL_OFF + dstoff, g_wl + boff);
        CP_COMMIT();
    };

    float acc[4][4][4];
    #pragma unroll
    for (int mt=0;mt<4;mt++)
        #pragma unroll
        for (int nt=0;nt<4;nt++)
            #pragma unroll
            for (int q=0;q<4;q++) acc[mt][nt][q] = 0.f;

    load_stage(0, 0);
    load_stage(1, 1);

    const int arow0 = wm*64 + (lane >> 2);
    const int acol  = (lane & 3)*2;
    const int brow0 = wn*32 + (lane >> 2);
    const int bcol  = (lane & 3)*2;

    for (int g=0; g<144; g++){
        const int buf = g % 3;
        CP_WAIT1();
        __syncthreads();
        if (g + 2 < 144) load_stage(g+2, (g+2)%3);

        const __half* Ah = (const __half*)(smem + buf*STG_SZ + AH_OFF);
        const __half* Al = (const __half*)(smem + buf*STG_SZ + AL_OFF);
        const __half* Bh = (const __half*)(smem + buf*STG_SZ + BH_OFF);
        const __half* Bl = (const __half*)(smem + buf*STG_SZ + BL_OFF);

        uint32_t ah[4][4], al[4][4], bh[4][2], bl[4][2];
        #pragma unroll
        for (int mt=0;mt<4;mt++){
            const int r = arow0 + mt*16;
            ah[mt][0] = *(const uint32_t*)(Ah + r*24      + acol);
            ah[mt][1] = *(const uint32_t*)(Ah + (r+8)*24  + acol);
            ah[mt][2] = *(const uint32_t*)(Ah + r*24      + acol + 8);
            ah[mt][3] = *(const uint32_t*)(Ah + (r+8)*24  + acol + 8);
            al[mt][0] = *(const uint32_t*)(Al + r*24      + acol);
            al[mt][1] = *(const uint32_t*)(Al + (r+8)*24  + acol);
            al[mt][2] = *(const uint32_t*)(Al + r*24      + acol + 8);
            al[mt][3] = *(const uint32_t*)(Al + (r+8)*24  + acol + 8);
        }
        #pragma unroll
        for (int nt=0;nt<4;nt++){
            const int n = brow0 + nt*8;
            bh[nt][0] = *(const uint32_t*)(Bh + n*24 + bcol);
            bh[nt][1] = *(const uint32_t*)(Bh + n*24 + bcol + 8);
            bl[nt][0] = *(const uint32_t*)(Bl + n*24 + bcol);
            bl[nt][1] = *(const uint32_t*)(Bl + n*24 + bcol + 8);
        }
        #pragma unroll
        for (int mt=0;mt<4;mt++)
            #pragma unroll
            for (int nt=0;nt<4;nt++){
                mma16816(acc[mt][nt], ah[mt], bh[nt]);
                mma16816(acc[mt][nt], ah[mt], bl[nt]);
                mma16816(acc[mt][nt], al[mt], bh[nt]);
            }
    }
    CP_WAIT0();

    // epilogue: bias + relu -> y NHWC
    #pragma unroll
    for (int nt=0;nt<4;nt++){
        const int cc = ocb + wn*32 + nt*8 + (lane & 3)*2;
        const float bz0 = b1[cc], bz1 = b1[cc+1];
        #pragma unroll
        for (int mt=0;mt<4;mt++){
            const int w = wm*64 + mt*16 + (lane >> 2);
            const size_t pix = (size_t)bb*HW + (size_t)h*WN + w;
            float2 v0, v1;
            v0.x = fmaxf(acc[mt][nt][0] + bz0, 0.f);
            v0.y = fmaxf(acc[mt][nt][1] + bz1, 0.f);
            v1.x = fmaxf(acc[mt][nt][2] + bz0, 0.f);
            v1.y = fmaxf(acc[mt][nt][3] + bz1, 0.f);
            *(float2*)&g_y[pix*CN + cc]       = v0;
            *(float2*)&g_y[(pix+8)*CN + cc]   = v1;
        }
    }
}

// ---------------- K2: conv1x1 + bias + softmax stats + logits out ----------
__global__ __launch_bounds__(256) void k2_conv1(const float* __restrict__ b2,
                                                float* __restrict__ out){
    __shared__ __align__(16) float ws2[32][84];
    const int tid = threadIdx.x;
    const int gp  = blockIdx.x*256 + tid;
    const int b   = gp >> 14, hw = gp & (HW-1);

    float acc[NCH];
    #pragma unroll
    for (int o=0;o<NCH;o++) acc[o] = 0.f;

    const float* yb = g_y + (size_t)gp*CN;      // NHWC: contiguous 256 per pixel
    for (int cc=0; cc<CN; cc+=32){
        __syncthreads();
        #pragma unroll
        for (int i=tid; i<32*NCH; i+=256)
            ws2[i/NCH][i%NCH] = g_w2t[(cc + i/NCH)*NCH + (i%NCH)];
        __syncthreads();
        float4 yv4[8];
        #pragma unroll
        for (int j=0;j<8;j++) yv4[j] = *(const float4*)(yb + cc + j*4);
        const float* yv = (const float*)yv4;
        #pragma unroll 4
        for (int cl=0; cl<32; cl++){
            const float v = yv[cl];
            #pragma unroll
            for (int o4=0;o4<20;o4++){
                float4 w4 = *(const float4*)&ws2[cl][o4*4];
                acc[o4*4+0] += v*w4.x; acc[o4*4+1] += v*w4.y;
                acc[o4*4+2] += v*w4.z; acc[o4*4+3] += v*w4.w;
            }
            acc[80] += v*ws2[cl][80];
        }
    }
    #pragma unroll
    for (int o=0;o<NCH;o++) acc[o] += b2[o];

    float m = acc[0];
    #pragma unroll
    for (int o=1;o<NCH;o++) m = fmaxf(m, acc[o]);
    float s = 0.f;
    #pragma unroll
    for (int o=0;o<NCH;o++) s += expf(acc[o]-m);
    int cls = 0; float best = acc[0];
    #pragma unroll
    for (int o=1;o<NCLS;o++) if (acc[o] > best){ best = acc[o]; cls = o; }

    g_pstar[gp] = expf(best - m)/s;
    g_cls[gp]   = cls;

    float* lo = out + 409600 + (size_t)b*NCH*HW + hw;
    #pragma unroll
    for (int o=0;o<NCH;o++) lo[(size_t)o*HW] = acc[o];
}

// ---------------- K3: local-max boost + score map --------------------------
__global__ void k3_boost(){
    const int gp = blockIdx.x*256 + threadIdx.x;
    const int b = gp>>14, hw = gp&(HW-1);
    const int h = hw>>7,  w  = hw&127;
    const float p = g_pstar[gp];
    const int   c = g_cls[gp];
    bool ok = (p >= 1e-6f);
    #pragma unroll
    for (int dy=-1; dy<=1; dy++)
        #pragma unroll
        for (int dx=-1; dx<=1; dx++){
            if (dy==0 && dx==0) continue;
            int nh = h+dy, nw = w+dx;
            if (nh<0 || nh>=HN || nw<0 || nw>=WN) continue;
            int n = (b<<14) + nh*WN + nw;
            if (g_cls[n]==c && p < g_pstar[n]) ok = false;
        }
    g_scores[gp] = p + (ok ? 1.f : 0.f);
}

// ---------------- K4: per-batch top-100 via bitonic sort -------------------
__global__ void k4_topk(){
    extern __shared__ unsigned long long sk[];
    const int N = HW;
    const int b = blockIdx.x, tid = threadIdx.x;
    for (int i=tid; i<N; i+=1024){
        unsigned sb2 = __float_as_uint(g_scores[(b<<14)+i]);
        sk[i] = ((unsigned long long)sb2<<32) | (unsigned)(0xFFFFFFFFu - (unsigned)i);
    }
    __syncthreads();
    for (int k=2; k<=N; k<<=1){
        for (int j=k>>1; j>0; j>>=1){
            for (int i=tid; i<N; i+=1024){
                int ixj = i^j;
                if (ixj > i){
                    unsigned long long a = sk[i], c = sk[ixj];
                    bool up = (i&k)==0;
                    if (up ? (a<c) : (a>c)){ sk[i]=c; sk[ixj]=a; }
                }
            }
            __syncthreads();
        }
    }
    if (tid < TK){
        unsigned low = (unsigned)sk[tid];
        g_topidx[b*TK + tid] = (int)(0xFFFFFFFFu - low);
    }
}

// ---------------- K5: gather proposals + pos embeddings --------------------
__global__ void k5_gather(const float* __restrict__ x,
                          const float* __restrict__ pe,
                          float* __restrict__ out){
    const int t = blockIdx.x*256 + threadIdx.x;
    if (t >= BN*CN*TK) return;
    const int k = t % TK;
    const int c = (t / TK) % CN;
    const int b = t / (TK*CN);
    const int idx = g_topidx[b*TK + k];
    out[t]            = x [(size_t)(b*CN + c)*HW + idx];
    out[BN*CN*TK + t] = pe[(size_t)c*HW + idx];
}

// ---------------- launch ----------------------------------------------------
extern "C" void kernel_launch(void* const* d_in, const int* in_sizes, int n_in,
                              void* d_out, int out_size){
    const float* x  = (const float*)d_in[0];
    const float* pe = (const float*)d_in[1];
    const float* w1 = (const float*)d_in[2];
    const float* b1 = (const float*)d_in[3];
    const float* w2 = (const float*)d_in[4];
    const float* b2 = (const float*)d_in[5];
    float* out = (float*)d_out;

    cudaFuncSetAttribute(kmma,   cudaFuncAttributeMaxDynamicSharedMemorySize, 3*STG_SZ);
    cudaFuncSetAttribute(k4_topk, cudaFuncAttributeMaxDynamicSharedMemorySize, 131072);

    dim3 gt((NPX + 31)/32, BN);
    t_half<<<gt, 256>>>(x);
    k0_wprep<<<(9*CN*CN + 255)/256, 256>>>(w1, w2);

    dim3 gg(128, 2, BN);
    kmma<<<gg, 256, 3*STG_SZ>>>(b1);

    k2_conv1<<<(BN*HW)/256, 256>>>(b2, out);
    k3_boost<<<(BN*HW)/256, 256>>>();
    k4_topk<<<BN, 1024, 131072>>>();
    k5_gather<<<(BN*CN*TK + 255)/256, 256>>>(x, pe, out);
}